// round 5
// baseline (speedup 1.0000x reference)
#include <cuda_runtime.h>
#include <cstdint>

// ---------------------------------------------------------------------------
// Swin window-MSA, fp32 with packed f32x2 FMA on the GEMMs.
//   B=64, L=3136 (56x56), C=96, H=3, E=32, window 7x7 (49 tokens), 8x8 windows
// ---------------------------------------------------------------------------

#define BATCH   64
#define IMG     56
#define WINSZ   7
#define NWIN    8          // windows per side
#define TOK     49         // tokens per window
#define HEADS   3
#define CDIM    96
#define EDIM    32
#define LDIM    3136
#define MROWS   200704     // BATCH * LDIM
#define WTOT    12288      // BATCH * HEADS * NWIN * NWIN

typedef unsigned long long u64;

// scratch (allocation-free rule: __device__ globals)
__device__ __align__(16) float g_Q[WTOT * TOK * EDIM];
__device__ __align__(16) float g_K[WTOT * TOK * EDIM];
__device__ __align__(16) float g_V[WTOT * TOK * EDIM];
__device__ __align__(16) float g_AO[MROWS * CDIM];

// ---- packed f32x2 helpers (sm_103a FFMA2 path) ----
__device__ __forceinline__ u64 pack2(float a, float b) {
    u64 r;
    asm("mov.b64 %0, {%1, %2};" : "=l"(r) : "f"(a), "f"(b));
    return r;
}
__device__ __forceinline__ u64 fma2(u64 a, u64 b, u64 c) {
    u64 d;
    asm("fma.rn.f32x2 %0, %1, %2, %3;" : "=l"(d) : "l"(a), "l"(b), "l"(c));
    return d;
}
__device__ __forceinline__ float2 unpack2(u64 v) {
    float2 f;
    asm("mov.b64 {%0, %1}, %2;" : "=f"(f.x), "=f"(f.y) : "l"(v));
    return f;
}

// ---------------------------------------------------------------------------
// Kernel 1: QKV GEMM + window scatter.
// grid (1568, 3): 128-row tile x head.  block 256.
// Thread (e = lane, rg = warp): 16 rows (two passes of 8), 3 outputs (q,k,v)
// per e. Rows paired for f32x2.
// ---------------------------------------------------------------------------
__global__ void __launch_bounds__(256) qkv_kernel(
    const float* __restrict__ x,
    const float* __restrict__ wqkv,
    const float* __restrict__ bqkv)
{
    __shared__ float wq[32 * 100], wk[32 * 100], wv[32 * 100];
    __shared__ int rowdst[128];

    const int tile = blockIdx.x;
    const int h    = blockIdx.y;
    const int tid  = threadIdx.x;

    // load weight panel transposed: wq[e][k] = wqkv[k][h*96 + 3e + 0], etc.
    for (int t = tid; t < 96 * 96; t += 256) {
        int k = t / 96, j = t - k * 96;
        float val = wqkv[k * 288 + h * 96 + j];
        int e = j / 3, kk = j - e * 3;
        float* dst = (kk == 0) ? wq : (kk == 1) ? wk : wv;
        dst[e * 100 + k] = val;
    }
    // per-row destination base in window layout
    if (tid < 128) {
        int gr  = tile * 128 + tid;
        int b   = gr / LDIM;
        int pix = gr - b * LDIM;
        int yy  = pix / IMG, xx = pix - yy * IMG;
        int win = (yy / WINSZ) * NWIN + (xx / WINSZ);
        int tok = (yy % WINSZ) * WINSZ + (xx % WINSZ);
        rowdst[tid] = (((b * HEADS + h) * (NWIN * NWIN) + win) * TOK + tok) * EDIM;
    }
    __syncthreads();

    const int e  = tid & 31;
    const int rg = tid >> 5;
    const float bq = bqkv[h * 96 + e * 3 + 0];
    const float bk = bqkv[h * 96 + e * 3 + 1];
    const float bv = bqkv[h * 96 + e * 3 + 2];

    #pragma unroll
    for (int pass = 0; pass < 2; pass++) {
        const int r0 = rg * 16 + pass * 8;
        const float* xb = x + ((size_t)tile * 128 + r0) * 96;

        u64 aq[4], ak[4], av[4];
        #pragma unroll
        for (int p = 0; p < 4; p++) {
            aq[p] = pack2(bq, bq);
            ak[p] = pack2(bk, bk);
            av[p] = pack2(bv, bv);
        }

        #pragma unroll 2
        for (int k4 = 0; k4 < 24; k4++) {
            float xr[32];
            #pragma unroll
            for (int r = 0; r < 8; r++) {
                float4 v = *(const float4*)(xb + (size_t)r * 96 + k4 * 4);
                xr[r * 4 + 0] = v.x; xr[r * 4 + 1] = v.y;
                xr[r * 4 + 2] = v.z; xr[r * 4 + 3] = v.w;
            }
            float4 w0 = *(const float4*)&wq[e * 100 + k4 * 4];
            float4 w1 = *(const float4*)&wk[e * 100 + k4 * 4];
            float4 w2 = *(const float4*)&wv[e * 100 + k4 * 4];
            u64 wqd[4] = {pack2(w0.x, w0.x), pack2(w0.y, w0.y),
                          pack2(w0.z, w0.z), pack2(w0.w, w0.w)};
            u64 wkd[4] = {pack2(w1.x, w1.x), pack2(w1.y, w1.y),
                          pack2(w1.z, w1.z), pack2(w1.w, w1.w)};
            u64 wvd[4] = {pack2(w2.x, w2.x), pack2(w2.y, w2.y),
                          pack2(w2.z, w2.z), pack2(w2.w, w2.w)};
            #pragma unroll
            for (int p = 0; p < 4; p++) {
                #pragma unroll
                for (int c = 0; c < 4; c++) {
                    u64 xp = pack2(xr[(2 * p) * 4 + c], xr[(2 * p + 1) * 4 + c]);
                    aq[p] = fma2(xp, wqd[c], aq[p]);
                    ak[p] = fma2(xp, wkd[c], ak[p]);
                    av[p] = fma2(xp, wvd[c], av[p]);
                }
            }
        }

        #pragma unroll
        for (int p = 0; p < 4; p++) {
            float2 fq = unpack2(aq[p]);
            float2 fk = unpack2(ak[p]);
            float2 fv = unpack2(av[p]);
            int d0 = rowdst[r0 + 2 * p] + e;
            int d1 = rowdst[r0 + 2 * p + 1] + e;
            g_Q[d0] = fq.x; g_K[d0] = fk.x; g_V[d0] = fv.x;
            g_Q[d1] = fq.y; g_K[d1] = fk.y; g_V[d1] = fv.y;
        }
    }
}

// ---------------------------------------------------------------------------
// Kernel 2: per-window attention.  grid 12288, block 64 (threads 0..48 own one
// query row each).  K/V/bias in smem; softmax fully thread-local.
// ---------------------------------------------------------------------------
__global__ void __launch_bounds__(64) attn_kernel(const float* __restrict__ rel_bias)
{
    __shared__ float4 Ks4[392];   // 49*32 floats
    __shared__ float4 Vs4[392];
    __shared__ float  Bs[TOK * TOK];

    const int widx = blockIdx.x;           // (b*3 + h)*64 + win
    const int tid  = threadIdx.x;

    const float* kb = g_K + (size_t)widx * (TOK * EDIM);
    const float* vb = g_V + (size_t)widx * (TOK * EDIM);
    for (int i = tid; i < 392; i += 64) {
        Ks4[i] = ((const float4*)kb)[i];
        Vs4[i] = ((const float4*)vb)[i];
    }
    for (int i = tid; i < TOK * TOK; i += 64) Bs[i] = rel_bias[i];
    __syncthreads();

    if (tid < TOK) {
        const float* qb = g_Q + (size_t)widx * (TOK * EDIM) + tid * EDIM;
        float4 q[8];
        #pragma unroll
        for (int t = 0; t < 8; t++) q[t] = ((const float4*)qb)[t];

        const float scale = 0.17677669529663687f;  // 1/sqrt(32)
        const float* Ks = (const float*)Ks4;
        const float* Vs = (const float*)Vs4;

        float s[TOK];
        float mx = -1e30f;
        #pragma unroll
        for (int j = 0; j < TOK; j++) {
            const float4* kr = (const float4*)(Ks + j * EDIM);
            float d = 0.f;
            #pragma unroll
            for (int t = 0; t < 8; t++) {
                float4 kv = kr[t];
                d += q[t].x * kv.x + q[t].y * kv.y + q[t].z * kv.z + q[t].w * kv.w;
            }
            d = d * scale + Bs[tid * TOK + j];
            s[j] = d;
            mx = fmaxf(mx, d);
        }
        float sum = 0.f;
        #pragma unroll
        for (int j = 0; j < TOK; j++) {
            s[j] = __expf(s[j] - mx);
            sum += s[j];
        }
        float inv = 1.0f / sum;

        float4 o[8];
        #pragma unroll
        for (int t = 0; t < 8; t++) o[t] = make_float4(0.f, 0.f, 0.f, 0.f);
        #pragma unroll
        for (int j = 0; j < TOK; j++) {
            float p = s[j];
            const float4* vr = (const float4*)(Vs + j * EDIM);
            #pragma unroll
            for (int t = 0; t < 8; t++) {
                float4 vv = vr[t];
                o[t].x += p * vv.x; o[t].y += p * vv.y;
                o[t].z += p * vv.z; o[t].w += p * vv.w;
            }
        }

        int b   = widx / (HEADS * NWIN * NWIN);
        int rem = widx - b * (HEADS * NWIN * NWIN);
        int h   = rem / (NWIN * NWIN);
        int win = rem - h * (NWIN * NWIN);
        int yy  = (win / NWIN) * WINSZ + tid / WINSZ;
        int xx  = (win % NWIN) * WINSZ + tid % WINSZ;
        float* dst = g_AO + ((size_t)b * LDIM + yy * IMG + xx) * CDIM + h * EDIM;
        #pragma unroll
        for (int t = 0; t < 8; t++) {
            float4 v = o[t];
            v.x *= inv; v.y *= inv; v.z *= inv; v.w *= inv;
            ((float4*)dst)[t] = v;
        }
    }
}

// ---------------------------------------------------------------------------
// Kernel 3: output projection GEMM.  grid 1568, block 256.
// Thread (e, rg): columns {e, e+32, e+64}, 16 rows (two passes of 8), rows
// paired for f32x2.  Writes coalesced (stride-1 per lane, per column group).
// ---------------------------------------------------------------------------
__global__ void __launch_bounds__(256) proj_kernel(
    const float* __restrict__ wproj,
    const float* __restrict__ bproj,
    float* __restrict__ out)
{
    __shared__ float w0s[32 * 100], w1s[32 * 100], w2s[32 * 100];

    const int tile = blockIdx.x;
    const int tid  = threadIdx.x;

    // wjs[e][k] = wproj[k][32*j + e]
    for (int t = tid; t < 96 * 96; t += 256) {
        int k = t / 96, c = t - k * 96;
        int j = c >> 5, e2 = c & 31;
        float* dst = (j == 0) ? w0s : (j == 1) ? w1s : w2s;
        dst[e2 * 100 + k] = wproj[t];
    }
    __syncthreads();

    const int e  = tid & 31;
    const int rg = tid >> 5;
    const float b0 = bproj[e];
    const float b1 = bproj[32 + e];
    const float b2 = bproj[64 + e];

    #pragma unroll
    for (int pass = 0; pass < 2; pass++) {
        const int r0 = rg * 16 + pass * 8;
        const float* xb = g_AO + ((size_t)tile * 128 + r0) * 96;

        u64 a0[4], a1[4], a2[4];
        #pragma unroll
        for (int p = 0; p < 4; p++) {
            a0[p] = pack2(b0, b0);
            a1[p] = pack2(b1, b1);
            a2[p] = pack2(b2, b2);
        }

        #pragma unroll 2
        for (int k4 = 0; k4 < 24; k4++) {
            float xr[32];
            #pragma unroll
            for (int r = 0; r < 8; r++) {
                float4 v = *(const float4*)(xb + (size_t)r * 96 + k4 * 4);
                xr[r * 4 + 0] = v.x; xr[r * 4 + 1] = v.y;
                xr[r * 4 + 2] = v.z; xr[r * 4 + 3] = v.w;
            }
            float4 w0 = *(const float4*)&w0s[e * 100 + k4 * 4];
            float4 w1 = *(const float4*)&w1s[e * 100 + k4 * 4];
            float4 w2 = *(const float4*)&w2s[e * 100 + k4 * 4];
            u64 w0d[4] = {pack2(w0.x, w0.x), pack2(w0.y, w0.y),
                          pack2(w0.z, w0.z), pack2(w0.w, w0.w)};
            u64 w1d[4] = {pack2(w1.x, w1.x), pack2(w1.y, w1.y),
                          pack2(w1.z, w1.z), pack2(w1.w, w1.w)};
            u64 w2d[4] = {pack2(w2.x, w2.x), pack2(w2.y, w2.y),
                          pack2(w2.z, w2.z), pack2(w2.w, w2.w)};
            #pragma unroll
            for (int p = 0; p < 4; p++) {
                #pragma unroll
                for (int c = 0; c < 4; c++) {
                    u64 xp = pack2(xr[(2 * p) * 4 + c], xr[(2 * p + 1) * 4 + c]);
                    a0[p] = fma2(xp, w0d[c], a0[p]);
                    a1[p] = fma2(xp, w1d[c], a1[p]);
                    a2[p] = fma2(xp, w2d[c], a2[p]);
                }
            }
        }

        float* ob = out + ((size_t)tile * 128 + r0) * 96;
        #pragma unroll
        for (int p = 0; p < 4; p++) {
            float2 f0 = unpack2(a0[p]);
            float2 f1 = unpack2(a1[p]);
            float2 f2 = unpack2(a2[p]);
            int o0 = (2 * p) * 96;
            int o1 = (2 * p + 1) * 96;
            ob[o0 + e]      = f0.x; ob[o1 + e]      = f0.y;
            ob[o0 + 32 + e] = f1.x; ob[o1 + 32 + e] = f1.y;
            ob[o0 + 64 + e] = f2.x; ob[o1 + 64 + e] = f2.y;
        }
    }
}

// ---------------------------------------------------------------------------
// Launch.  Inputs (metadata order): x, w_qkv, b_qkv, w_proj, b_proj, rel_bias.
// ---------------------------------------------------------------------------
extern "C" void kernel_launch(void* const* d_in, const int* in_sizes, int n_in,
                              void* d_out, int out_size)
{
    (void)in_sizes; (void)n_in; (void)out_size;
    const float* x        = (const float*)d_in[0];
    const float* w_qkv    = (const float*)d_in[1];
    const float* b_qkv    = (const float*)d_in[2];
    const float* w_proj   = (const float*)d_in[3];
    const float* b_proj   = (const float*)d_in[4];
    const float* rel_bias = (const float*)d_in[5];
    float* out = (float*)d_out;

    qkv_kernel<<<dim3(1568, 3), 256>>>(x, w_qkv, b_qkv);
    attn_kernel<<<WTOT, 64>>>(rel_bias);
    proj_kernel<<<1568, 256>>>(w_proj, b_proj, out);
}